// round 7
// baseline (speedup 1.0000x reference)
#include <cuda_runtime.h>
#include <cstdint>

#define VOCAB 50000
#define EDIM  256
#define HDIM  256
#define BATCH 64
#define TLEN  2048

typedef unsigned long long u64;

// proj_table[v][h] = sum_e emb[v][e] * W_ih[h][e]   (51.2 MB device scratch)
__device__ float g_proj[VOCAB * HDIM];

// ---------------------------------------------------------------------------
// Kernel A: proj = emb @ W_ih^T   (NT SGEMM, C[50000,256])  -- unchanged
// ---------------------------------------------------------------------------
__global__ __launch_bounds__(256) void proj_kernel(const float* __restrict__ emb,
                                                   const float* __restrict__ Wih) {
    __shared__ float As[32][128];
    __shared__ float Bs[32][128];

    const int n0 = blockIdx.x * 128;
    const int m0 = blockIdx.y * 128;
    const int tid = threadIdx.x;
    const int tx = tid & 15;
    const int ty = tid >> 4;

    float acc[8][8];
#pragma unroll
    for (int a = 0; a < 8; a++)
#pragma unroll
        for (int bb = 0; bb < 8; bb++) acc[a][bb] = 0.0f;

    for (int kc = 0; kc < EDIM; kc += 32) {
#pragma unroll
        for (int q = 0; q < 4; q++) {
            int fid = tid + 256 * q;
            int row = fid >> 3;
            int col = fid & 7;
            float4 av = make_float4(0.f, 0.f, 0.f, 0.f);
            int m = m0 + row;
            if (m < VOCAB)
                av = __ldg((const float4*)(emb + (size_t)m * EDIM + kc + col * 4));
            As[col * 4 + 0][row] = av.x;
            As[col * 4 + 1][row] = av.y;
            As[col * 4 + 2][row] = av.z;
            As[col * 4 + 3][row] = av.w;
            float4 bv = __ldg((const float4*)(Wih + (size_t)(n0 + row) * EDIM + kc + col * 4));
            Bs[col * 4 + 0][row] = bv.x;
            Bs[col * 4 + 1][row] = bv.y;
            Bs[col * 4 + 2][row] = bv.z;
            Bs[col * 4 + 3][row] = bv.w;
        }
        __syncthreads();

#pragma unroll
        for (int k = 0; k < 32; k++) {
            float a[8], b[8];
            *(float4*)&a[0] = *(const float4*)&As[k][ty * 8];
            *(float4*)&a[4] = *(const float4*)&As[k][ty * 8 + 4];
            *(float4*)&b[0] = *(const float4*)&Bs[k][tx * 8];
            *(float4*)&b[4] = *(const float4*)&Bs[k][tx * 8 + 4];
#pragma unroll
            for (int ii = 0; ii < 8; ii++)
#pragma unroll
                for (int jj = 0; jj < 8; jj++) acc[ii][jj] += a[ii] * b[jj];
        }
        __syncthreads();
    }

#pragma unroll
    for (int ii = 0; ii < 8; ii++) {
        int m = m0 + ty * 8 + ii;
        if (m < VOCAB) {
            float4 v0 = make_float4(acc[ii][0], acc[ii][1], acc[ii][2], acc[ii][3]);
            float4 v1 = make_float4(acc[ii][4], acc[ii][5], acc[ii][6], acc[ii][7]);
            *(float4*)(g_proj + (size_t)m * HDIM + n0 + tx * 8)     = v0;
            *(float4*)(g_proj + (size_t)m * HDIM + n0 + tx * 8 + 4) = v1;
        }
    }
}

// ---------------------------------------------------------------------------
// Kernel B: RNN scan. 64 clusters x 2 CTAs of 1024 threads.
// NO per-step cluster barrier: peer h arrives via st.shared::cluster, and
// each producer warp posts a monotonic flag (t+1) into the peer's flags[w]
// with st.release.cluster (A-cumulative over the warp's value stores via
// __syncwarp). Consumers poll local flags[] with ld.acquire.cluster.
// Warp layout (R2): warp w owns outputs w*4..w*4+3, lane group g=l&7 covers
// 32 K each (16 own-half before the wait, 16 peer-half after). 3-shfl reduce.
// One __syncthreads per step (after flag post, off the cross-CTA path).
// ---------------------------------------------------------------------------
__device__ __forceinline__ void fma2(u64& acc, u64 a, u64 b) {
    asm("fma.rn.f32x2 %0, %1, %2, %0;" : "+l"(acc) : "l"(a), "l"(b));
}
__device__ __forceinline__ uint32_t s2u(const void* p) {
    return (uint32_t)__cvta_generic_to_shared(p);
}
__device__ __forceinline__ uint32_t mapa_u32(uint32_t a, uint32_t r) {
    uint32_t ret;
    asm("mapa.shared::cluster.u32 %0, %1, %2;" : "=r"(ret) : "r"(a), "r"(r));
    return ret;
}
__device__ __forceinline__ void st_remote_f32(uint32_t ra, float v) {
    asm volatile("st.shared::cluster.f32 [%0], %1;" :: "r"(ra), "f"(v) : "memory");
}
__device__ __forceinline__ void st_release_remote_u32(uint32_t ra, uint32_t v) {
    asm volatile("st.release.cluster.shared::cluster.u32 [%0], %1;"
                 :: "r"(ra), "r"(v) : "memory");
}
__device__ __forceinline__ uint32_t ld_acquire_u32(uint32_t a) {
    uint32_t v;
    asm volatile("ld.acquire.cluster.shared::cta.u32 %0, [%1];"
                 : "=r"(v) : "r"(a) : "memory");
    return v;
}
__device__ __forceinline__ void cl_arrive() {
    asm volatile("barrier.cluster.arrive.aligned;" ::: "memory");
}
__device__ __forceinline__ void cl_wait() {
    asm volatile("barrier.cluster.wait.aligned;" ::: "memory");
}
// exact-enough tanh (validated rel_err ~2.8e-7 end-to-end in R5)
__device__ __forceinline__ float fast_tanh(float x) {
    float xc = fminf(fmaxf(x, -15.0f), 15.0f);
    float e  = __expf(2.0f * xc);
    return __fdividef(e - 1.0f, e + 1.0f);
}

__global__ void __cluster_dims__(2, 1, 1) __launch_bounds__(1024, 1)
scan_kernel(const int* __restrict__ reviews, const int* __restrict__ lengths,
            const float* __restrict__ Whh, const float* __restrict__ Wcls,
            const float* __restrict__ bcls, float* __restrict__ out) {
    __shared__ __align__(16) float hbuf[2][HDIM];   // both halves, double-buffered
    __shared__ uint32_t flags[32];                  // peer warp w's progress tag
    __shared__ int toks[TLEN];

    const int tid  = threadIdx.x;
    const int w    = tid >> 5;              // 32 warps
    const int l    = tid & 31;
    const int g    = l & 7;                 // K-slice within output group
    const int i    = w * 4 + (l >> 3);      // local output index 0..127
    const int b    = blockIdx.x >> 1;
    const int rank = blockIdx.x & 1;
    const int peer = rank ^ 1;
    const int len  = lengths[b];
    const int ownK  = rank * 128;           // h range produced locally
    const int peerK = 128 - ownK;

    for (int idx = tid; idx < TLEN; idx += 1024)
        toks[idx] = reviews[b * TLEN + idx];
    if (tid < HDIM) hbuf[0][tid] = 0.0f;
    if (tid < 32)   flags[tid] = 0u;

    // W_hh[ownK+i][.] split own-half / peer-half K, packed f32x2 (R2 layout)
    u64 wOwn[8], wPeer[8];
    {
        const float* wr = Whh + (size_t)(ownK + i) * HDIM;
#pragma unroll
        for (int q = 0; q < 4; q++) {
            ulonglong2 a = *(const ulonglong2*)(wr + ownK + q * 32 + g * 4);
            wOwn[2 * q]     = a.x;
            wOwn[2 * q + 1] = a.y;
            ulonglong2 c = *(const ulonglong2*)(wr + peerK + q * 32 + g * 4);
            wPeer[2 * q]     = c.x;
            wPeer[2 * q + 1] = c.y;
        }
    }
    __syncthreads();
    // peer's flags zero-init must be visible before we can post flags there
    cl_arrive();
    cl_wait();

    const int ow = ownK + i;
    const uint32_t rH0 = mapa_u32(s2u(&hbuf[0][ow]), peer);
    const uint32_t rH1 = mapa_u32(s2u(&hbuf[1][ow]), peer);
    const uint32_t rF  = mapa_u32(s2u(&flags[w]), peer);
    const uint32_t fa  = s2u(&flags[l]);    // lane l polls peer warp l's tag

    float xp_cur = __ldg(g_proj + (size_t)toks[0] * HDIM + ow);

    for (int t = 0; t < len; ++t) {
        const int p = t & 1, pn = p ^ 1;

        // prefetch next step's xp (hidden under FMA + poll)
        int tn = (t + 1 < len) ? (t + 1) : t;
        float xp_next = __ldg(g_proj + (size_t)toks[tn] * HDIM + ow);

        const float* hb = hbuf[p];
        u64 a0 = 0ull, a1 = 0ull, a2 = 0ull, a3 = 0ull;
        // own-half K: locally produced, guarded by prior __syncthreads
#pragma unroll
        for (int q = 0; q < 4; q++) {
            ulonglong2 hh = *(const ulonglong2*)(hb + ownK + q * 32 + g * 4);
            fma2((q & 1) ? a1 : a0, wOwn[2 * q],     hh.x);
            fma2((q & 1) ? a3 : a2, wOwn[2 * q + 1], hh.y);
        }
        // wait for peer's half: all 32 peer warps posted tag >= t
        {
            uint32_t f;
            do { f = ld_acquire_u32(fa); }
            while (__any_sync(0xffffffffu, (int)f < t));
        }
#pragma unroll
        for (int q = 0; q < 4; q++) {
            ulonglong2 hh = *(const ulonglong2*)(hb + peerK + q * 32 + g * 4);
            fma2((q & 1) ? a1 : a0, wPeer[2 * q],     hh.x);
            fma2((q & 1) ? a3 : a2, wPeer[2 * q + 1], hh.y);
        }
        float2 f0 = *(float2*)&a0, f1 = *(float2*)&a1;
        float2 f2 = *(float2*)&a2, f3 = *(float2*)&a3;
        float sum = (f0.x + f0.y) + (f1.x + f1.y) + (f2.x + f2.y) + (f3.x + f3.y);
        sum += __shfl_xor_sync(0xffffffffu, sum, 1);
        sum += __shfl_xor_sync(0xffffffffu, sum, 2);
        sum += __shfl_xor_sync(0xffffffffu, sum, 4);

        float v = fast_tanh(sum + xp_cur);  // uniform across the 8-lane group
        xp_cur = xp_next;
        if (g == 0) {
            hbuf[pn][ow] = v;               // local copy
            st_remote_f32(pn ? rH1 : rH0, v);   // peer copy (DSMEM)
        }
        __syncwarp();                       // order warp's 4 value stores...
        if (l == 0) st_release_remote_u32(rF, (uint32_t)(t + 1)); // ...before tag
        __syncthreads();                    // local half visible CTA-wide
    }

    // classifier: rank 0 assembles full final h
    if (rank == 0 && tid < 64) {
        // peer's final half: all 32 peer tags >= len
        {
            uint32_t f;
            do { f = ld_acquire_u32(fa); }
            while (__any_sync(0xffffffffu, (int)f < len));
        }
        int c = tid >> 5, lane = tid & 31;
        const float* hf = hbuf[len & 1];
        float sum = 0.0f;
#pragma unroll
        for (int m = 0; m < 8; m++)
            sum += Wcls[c * HDIM + lane + 32 * m] * hf[lane + 32 * m];
#pragma unroll
        for (int o = 16; o > 0; o >>= 1) sum += __shfl_down_sync(0xffffffffu, sum, o);
        if (lane == 0) out[b * 2 + c] = sum + bcls[c];
    }

    // keep both CTAs alive until all cross-CTA traffic has landed
    cl_arrive();
    cl_wait();
}

// ---------------------------------------------------------------------------
extern "C" void kernel_launch(void* const* d_in, const int* in_sizes, int n_in,
                              void* d_out, int out_size) {
    const int*   reviews = (const int*)d_in[0];
    const int*   lengths = (const int*)d_in[1];
    const float* emb     = (const float*)d_in[2];
    const float* Wih     = (const float*)d_in[3];
    const float* Whh     = (const float*)d_in[4];
    const float* Wcls    = (const float*)d_in[5];
    const float* bcls    = (const float*)d_in[6];
    float*       out     = (float*)d_out;

    dim3 gA(2, (VOCAB + 127) / 128);
    proj_kernel<<<gA, 256>>>(emb, Wih);

    scan_kernel<<<BATCH * 2, 1024>>>(reviews, lengths, Whh, Wcls, bcls, out);
}

// round 8
// speedup vs baseline: 1.0995x; 1.0995x over previous
#include <cuda_runtime.h>
#include <cstdint>

#define VOCAB 50000
#define EDIM  256
#define HDIM  256
#define BATCH 64
#define TLEN  2048

typedef unsigned long long u64;

// proj_table[v][h] = sum_e emb[v][e] * W_ih[h][e]   (51.2 MB device scratch)
__device__ float g_proj[VOCAB * HDIM];

// ---------------------------------------------------------------------------
// Kernel A: proj = emb @ W_ih^T   (NT SGEMM, C[50000,256])  -- unchanged
// ---------------------------------------------------------------------------
__global__ __launch_bounds__(256) void proj_kernel(const float* __restrict__ emb,
                                                   const float* __restrict__ Wih) {
    __shared__ float As[32][128];
    __shared__ float Bs[32][128];

    const int n0 = blockIdx.x * 128;
    const int m0 = blockIdx.y * 128;
    const int tid = threadIdx.x;
    const int tx = tid & 15;
    const int ty = tid >> 4;

    float acc[8][8];
#pragma unroll
    for (int a = 0; a < 8; a++)
#pragma unroll
        for (int bb = 0; bb < 8; bb++) acc[a][bb] = 0.0f;

    for (int kc = 0; kc < EDIM; kc += 32) {
#pragma unroll
        for (int q = 0; q < 4; q++) {
            int fid = tid + 256 * q;
            int row = fid >> 3;
            int col = fid & 7;
            float4 av = make_float4(0.f, 0.f, 0.f, 0.f);
            int m = m0 + row;
            if (m < VOCAB)
                av = __ldg((const float4*)(emb + (size_t)m * EDIM + kc + col * 4));
            As[col * 4 + 0][row] = av.x;
            As[col * 4 + 1][row] = av.y;
            As[col * 4 + 2][row] = av.z;
            As[col * 4 + 3][row] = av.w;
            float4 bv = __ldg((const float4*)(Wih + (size_t)(n0 + row) * EDIM + kc + col * 4));
            Bs[col * 4 + 0][row] = bv.x;
            Bs[col * 4 + 1][row] = bv.y;
            Bs[col * 4 + 2][row] = bv.z;
            Bs[col * 4 + 3][row] = bv.w;
        }
        __syncthreads();

#pragma unroll
        for (int k = 0; k < 32; k++) {
            float a[8], b[8];
            *(float4*)&a[0] = *(const float4*)&As[k][ty * 8];
            *(float4*)&a[4] = *(const float4*)&As[k][ty * 8 + 4];
            *(float4*)&b[0] = *(const float4*)&Bs[k][tx * 8];
            *(float4*)&b[4] = *(const float4*)&Bs[k][tx * 8 + 4];
#pragma unroll
            for (int ii = 0; ii < 8; ii++)
#pragma unroll
                for (int jj = 0; jj < 8; jj++) acc[ii][jj] += a[ii] * b[jj];
        }
        __syncthreads();
    }

#pragma unroll
    for (int ii = 0; ii < 8; ii++) {
        int m = m0 + ty * 8 + ii;
        if (m < VOCAB) {
            float4 v0 = make_float4(acc[ii][0], acc[ii][1], acc[ii][2], acc[ii][3]);
            float4 v1 = make_float4(acc[ii][4], acc[ii][5], acc[ii][6], acc[ii][7]);
            *(float4*)(g_proj + (size_t)m * HDIM + n0 + tx * 8)     = v0;
            *(float4*)(g_proj + (size_t)m * HDIM + n0 + tx * 8 + 4) = v1;
        }
    }
}

// ---------------------------------------------------------------------------
// Kernel B: RNN scan. 64 clusters x 2 CTAs of 1024 threads.
// Sync skeleton = R1 (fastest measured): st.shared::cluster h exchange +
// one barrier.cluster arrive/wait per step, own-half FMAs issued before the
// wait. Local cuts vs R1: warp-local 3-shfl reduce (one __syncthreads/step
// instead of two + smem ps), fast exp-based tanh, cl_arrive hoisted before
// __syncthreads.
// Warp layout: warp w owns outputs w*4..w*4+3; lane group g=l&7 covers 32 K
// (16 own-half before the wait, 16 peer-half after). h reads broadcast
// across the 4 same-g lanes; 8 distinct 16B chunks per LDS.128 -> 1 phase.
// ---------------------------------------------------------------------------
__device__ __forceinline__ void fma2(u64& acc, u64 a, u64 b) {
    asm("fma.rn.f32x2 %0, %1, %2, %0;" : "+l"(acc) : "l"(a), "l"(b));
}
__device__ __forceinline__ uint32_t s2u(const void* p) {
    return (uint32_t)__cvta_generic_to_shared(p);
}
__device__ __forceinline__ uint32_t mapa_u32(uint32_t a, uint32_t r) {
    uint32_t ret;
    asm("mapa.shared::cluster.u32 %0, %1, %2;" : "=r"(ret) : "r"(a), "r"(r));
    return ret;
}
__device__ __forceinline__ void st_remote_f32(uint32_t ra, float v) {
    asm volatile("st.shared::cluster.f32 [%0], %1;" :: "r"(ra), "f"(v) : "memory");
}
__device__ __forceinline__ void cl_arrive() {
    asm volatile("barrier.cluster.arrive.aligned;" ::: "memory");
}
__device__ __forceinline__ void cl_wait() {
    asm volatile("barrier.cluster.wait.aligned;" ::: "memory");
}
// exact-enough tanh (validated rel_err ~2.7e-7 end-to-end in R5/R6)
__device__ __forceinline__ float fast_tanh(float x) {
    float xc = fminf(fmaxf(x, -15.0f), 15.0f);
    float e  = __expf(2.0f * xc);
    return __fdividef(e - 1.0f, e + 1.0f);
}

__global__ void __cluster_dims__(2, 1, 1) __launch_bounds__(1024, 1)
scan_kernel(const int* __restrict__ reviews, const int* __restrict__ lengths,
            const float* __restrict__ Whh, const float* __restrict__ Wcls,
            const float* __restrict__ bcls, float* __restrict__ out) {
    __shared__ __align__(16) float hbuf[2][HDIM];   // full h, double-buffered
    __shared__ int toks[TLEN];

    const int tid  = threadIdx.x;
    const int w    = tid >> 5;              // 32 warps
    const int l    = tid & 31;
    const int g    = l & 7;                 // K-slice within output group
    const int i    = w * 4 + (l >> 3);      // local output index 0..127
    const int b    = blockIdx.x >> 1;
    const int rank = blockIdx.x & 1;
    const int peer = rank ^ 1;
    const int len  = lengths[b];
    const int ownK  = rank * 128;           // h range produced locally
    const int peerK = 128 - ownK;

    for (int idx = tid; idx < TLEN; idx += 1024)
        toks[idx] = reviews[b * TLEN + idx];
    if (tid < HDIM) hbuf[0][tid] = 0.0f;

    // W_hh[ownK+i][.] split own-half / peer-half K, packed f32x2
    u64 wOwn[8], wPeer[8];
    {
        const float* wr = Whh + (size_t)(ownK + i) * HDIM;
#pragma unroll
        for (int q = 0; q < 4; q++) {
            ulonglong2 a = *(const ulonglong2*)(wr + ownK + q * 32 + g * 4);
            wOwn[2 * q]     = a.x;
            wOwn[2 * q + 1] = a.y;
            ulonglong2 c = *(const ulonglong2*)(wr + peerK + q * 32 + g * 4);
            wPeer[2 * q]     = c.x;
            wPeer[2 * q + 1] = c.y;
        }
    }
    __syncthreads();

    const int ow = ownK + i;
    const uint32_t rH0 = mapa_u32(s2u(&hbuf[0][ow]), peer);
    const uint32_t rH1 = mapa_u32(s2u(&hbuf[1][ow]), peer);

    float xp_cur = __ldg(g_proj + (size_t)toks[0] * HDIM + ow);

    // prologue arrive (pairs with t=0 wait; hbuf[0] fully zeroed locally)
    cl_arrive();

    for (int t = 0; t < len; ++t) {
        const int p = t & 1, pn = p ^ 1;

        // prefetch next step's xp (hidden under FMA + wait)
        int tn = (t + 1 < len) ? (t + 1) : t;
        float xp_next = __ldg(g_proj + (size_t)toks[tn] * HDIM + ow);

        const float* hb = hbuf[p];
        u64 a0 = 0ull, a1 = 0ull, a2 = 0ull, a3 = 0ull;
        // own-half K: locally produced, guarded by prior __syncthreads
#pragma unroll
        for (int q = 0; q < 4; q++) {
            ulonglong2 hh = *(const ulonglong2*)(hb + ownK + q * 32 + g * 4);
            fma2((q & 1) ? a1 : a0, wOwn[2 * q],     hh.x);
            fma2((q & 1) ? a3 : a2, wOwn[2 * q + 1], hh.y);
        }
        // wait: peer's h-half stores from step t-1 now visible
        cl_wait();
#pragma unroll
        for (int q = 0; q < 4; q++) {
            ulonglong2 hh = *(const ulonglong2*)(hb + peerK + q * 32 + g * 4);
            fma2((q & 1) ? a1 : a0, wPeer[2 * q],     hh.x);
            fma2((q & 1) ? a3 : a2, wPeer[2 * q + 1], hh.y);
        }
        float2 f0 = *(float2*)&a0, f1 = *(float2*)&a1;
        float2 f2 = *(float2*)&a2, f3 = *(float2*)&a3;
        float sum = (f0.x + f0.y) + (f1.x + f1.y) + (f2.x + f2.y) + (f3.x + f3.y);
        sum += __shfl_xor_sync(0xffffffffu, sum, 1);
        sum += __shfl_xor_sync(0xffffffffu, sum, 2);
        sum += __shfl_xor_sync(0xffffffffu, sum, 4);

        float v = fast_tanh(sum + xp_cur);  // uniform across the 8-lane group
        xp_cur = xp_next;
        if (g == 0) {
            hbuf[pn][ow] = v;                   // local copy
            st_remote_f32(pn ? rH1 : rH0, v);   // peer copy (DSMEM)
        }
        cl_arrive();        // release remote stores; peer can wake early
        __syncthreads();    // local half visible CTA-wide (off cross-CTA path)
    }
    cl_wait();              // final exchange visible

    // classifier: rank 0 has the full final h
    if (rank == 0 && tid < 64) {
        int c = tid >> 5, lane = tid & 31;
        const float* hf = hbuf[len & 1];
        float sum = 0.0f;
#pragma unroll
        for (int m = 0; m < 8; m++)
            sum += Wcls[c * HDIM + lane + 32 * m] * hf[lane + 32 * m];
#pragma unroll
        for (int o = 16; o > 0; o >>= 1) sum += __shfl_down_sync(0xffffffffu, sum, o);
        if (lane == 0) out[b * 2 + c] = sum + bcls[c];
    }

    // keep both CTAs alive until all cross-CTA traffic has landed
    cl_arrive();
    cl_wait();
}

// ---------------------------------------------------------------------------
extern "C" void kernel_launch(void* const* d_in, const int* in_sizes, int n_in,
                              void* d_out, int out_size) {
    const int*   reviews = (const int*)d_in[0];
    const int*   lengths = (const int*)d_in[1];
    const float* emb     = (const float*)d_in[2];
    const float* Wih     = (const float*)d_in[3];
    const float* Whh     = (const float*)d_in[4];
    const float* Wcls    = (const float*)d_in[5];
    const float* bcls    = (const float*)d_in[6];
    float*       out     = (float*)d_out;

    dim3 gA(2, (VOCAB + 127) / 128);
    proj_kernel<<<gA, 256>>>(emb, Wih);

    scan_kernel<<<BATCH * 2, 1024>>>(reviews, lengths, Whh, Wcls, bcls, out);
}